// round 13
// baseline (speedup 1.0000x reference)
#include <cuda_runtime.h>

typedef unsigned long long u64;

// ---------------- problem constants ----------------
#define BB    64
#define MAXV  200
#define PP    40
#define DOTH  57
#define KK    100
#define TTA   8      // rows per block in kernel A (25 * 8 = 200 rows)
#define NTA   25
#define TTC   10     // t-steps per block in kernel C (20 * 10 = 200 >= 198)
#define NTC   20
#define TOUT  198
#define HID   256

// Per-batch tgt contributions (time-invariant)
__device__ float g_tgtF[BB * HID];
__device__ float g_tgtB[BB * HID];
// h1 scratch (duplicated f32x2 format): ~26 MB, zero-init at module load
__device__ u64 g_h1d[(size_t)BB * MAXV * HID];

// ---------------- packed f32x2 helpers ----------------
__device__ __forceinline__ u64 f2fma(u64 a, u64 b, u64 c) {
    u64 d; asm("fma.rn.f32x2 %0,%1,%2,%3;" : "=l"(d) : "l"(a), "l"(b), "l"(c)); return d;
}
__device__ __forceinline__ u64 f2add(u64 a, u64 b) {
    u64 d; asm("add.rn.f32x2 %0,%1,%2;" : "=l"(d) : "l"(a), "l"(b)); return d;
}
__device__ __forceinline__ u64 dup2(float v) {
    u64 d; asm("mov.b64 %0,{%1,%1};" : "=l"(d) : "f"(v)); return d;
}
__device__ __forceinline__ void unpack2(u64 v, float& x, float& y) {
    asm("mov.b64 {%0,%1},%2;" : "=f"(x), "=f"(y) : "l"(v));
}
__device__ __forceinline__ u64 ldg2(const float* __restrict__ p) {
    return *reinterpret_cast<const u64*>(p);
}
__device__ __forceinline__ ulonglong2 ldg4(const float* __restrict__ p) {
    return *reinterpret_cast<const ulonglong2*>(p);
}

// ---------------------------------------------------------------------------
// Kernel 1: per-batch tgt @ Wf[507:607] / Wb[507:607].
// Multiply-form (kf in {0,1}) -> unconditional fully-unrolled LDG stream.
// Threads 0-127: Wf col-pairs; 128-255: Wb col-pairs.
// ---------------------------------------------------------------------------
__global__ __launch_bounds__(256) void tgt_kernel(
    const int* __restrict__ target, const int* __restrict__ widx,
    const float* __restrict__ Wf, const float* __restrict__ Wb)
{
    __shared__ int s_t[10];
    __shared__ u64 s_kf2[KK];   // keep flag duplicated as f32x2
    const int b = blockIdx.x;
    const int j = threadIdx.x;
    if (j < 10) s_t[j] = target[b * 10 + j];
    __syncthreads();
    if (j < KK) {
        int w = widx[j];
        int keep = 1;
        #pragma unroll
        for (int q = 0; q < 10; q++) keep &= (s_t[q] != w);
        s_kf2[j] = dup2(keep ? 1.f : 0.f);
    }
    __syncthreads();
    const int m  = j >> 7;
    const int c0 = 2 * (j & 127);
    const float* W = m ? Wb : Wf;
    u64 a = 0ull;
    #pragma unroll 10
    for (int k = 0; k < KK; k++)
        a = f2fma(s_kf2[k], ldg2(W + (size_t)(507 + k) * HID + c0), a);
    float* dst = m ? g_tgtB : g_tgtF;
    *reinterpret_cast<u64*>(&dst[b * HID + c0]) = a;
}

// ---------------------------------------------------------------------------
// Dedup within each row of PP codes (multi_hot duplicate collapse). -1 = skip.
// ---------------------------------------------------------------------------
__device__ __forceinline__ void dedup_codes(const int* __restrict__ s_codes,
                                            int* __restrict__ s_out, int j)
{
    for (int idx = j; idx < TTA * PP; idx += 256) {
        int p = idx % PP;
        int base = idx - p;
        int c = s_codes[idx];
        int take = 1;
        for (int q = 0; q < p; q++) take &= (s_codes[base + q] != c);
        s_out[idx] = take ? c : -1;
    }
}

// ---------------------------------------------------------------------------
// Dense feature accumulate: 2 rows x 4 cols, LDG.128 weights.
// ---------------------------------------------------------------------------
__device__ __forceinline__ void dense_acc2(
    u64 (* __restrict__ acc)[2], const u64* __restrict__ sc, int stride, int nd,
    const float* __restrict__ W, int row0, int rbase, int c0)
{
    int i = 0;
    for (; i + 1 < nd; i += 2) {
        ulonglong2 wA = ldg4(W + (size_t)(row0 + i) * HID + c0);
        ulonglong2 wB = ldg4(W + (size_t)(row0 + i + 1) * HID + c0);
        #pragma unroll
        for (int lr = 0; lr < 2; lr++) {
            ulonglong2 s = *reinterpret_cast<const ulonglong2*>(&sc[(rbase + lr) * stride + i]);
            acc[lr][0] = f2fma(s.x, wA.x, acc[lr][0]);
            acc[lr][1] = f2fma(s.x, wA.y, acc[lr][1]);
            acc[lr][0] = f2fma(s.y, wB.x, acc[lr][0]);
            acc[lr][1] = f2fma(s.y, wB.y, acc[lr][1]);
        }
    }
    if (i < nd) {
        ulonglong2 wA = ldg4(W + (size_t)(row0 + i) * HID + c0);
        #pragma unroll
        for (int lr = 0; lr < 2; lr++) {
            u64 s = sc[(rbase + lr) * stride + i];
            acc[lr][0] = f2fma(s, wA.x, acc[lr][0]);
            acc[lr][1] = f2fma(s, wA.y, acc[lr][1]);
        }
    }
}

// ---------------------------------------------------------------------------
// Kernel A: unified per-row gathers, UNIFORM quad mapping.
// Block = (b, 8 rows v). Thread = (col-quad q of 4 cols, row-group g of 2 rows).
// One code stage + one dedup drives Wf/Wb/W0 gathers via LDG.128.
// ---------------------------------------------------------------------------
__global__ __launch_bounds__(256, 5) void kernelA(
    const int*   __restrict__ code,   const float* __restrict__ others,
    const int*   __restrict__ length,
    const float* __restrict__ Wf, const float* __restrict__ bf,
    const float* __restrict__ Wb, const float* __restrict__ bb,
    const float* __restrict__ W0, const float* __restrict__ b0,
    float* __restrict__ outF, float* __restrict__ outB)
{
    __shared__ int s_codes[TTA * PP];
    __shared__ int s_codes2[TTA * PP];
    __shared__ __align__(16) u64 s_scF[TTA * 58];
    __shared__ __align__(16) u64 s_scB[TTA * 58];
    __shared__ __align__(16) u64 s_scV[TTA * 48];

    const int b  = blockIdx.y;
    const int v0 = blockIdx.x * TTA;
    const int j  = threadIdx.x;
    const int q  = j & 63;
    const int g  = j >> 6;          // 4 row-groups of 2 rows (uniform)
    const int c0 = q * 4;
    const int rbase = g * 2;
    const int L  = length[b];
    const bool fvA = (v0 <= L - 2);

    const float* oth = others + (size_t)b * MAXV * DOTH;
    const int*   cod = code   + (size_t)b * MAXV * PP;

    // ---- stage codes ----
    for (int idx = j; idx < TTA * PP; idx += 256) {
        int r = idx / PP, p = idx - r * PP;
        s_codes[idx] = cod[(v0 + r) * PP + p];
    }
    // ---- stage forward scalars (57) ----
    for (int idx = j; idx < TTA * 57; idx += 256) {
        int r = idx / 57, i = idx - r * 57;
        int col = (i < 27) ? i : ((i < 47) ? i + 10 : i - 20);
        s_scF[r * 58 + i] = dup2(oth[(v0 + r) * DOTH + col]);
    }
    // ---- stage backward scalars (57): 0..46 = feature(v), 47..56 = interval(w(v)) ----
    for (int idx = j; idx < TTA * 57; idx += 256) {
        int r = idx / 57, i = idx - r * 57;
        int v = v0 + r;
        float val;
        if (i < 47) {
            int col = (i < 27) ? i : i + 10;
            val = oth[v * DOTH + col];
        } else {
            if (v == L - 1) val = 0.f;
            else {
                int w = (v <= L - 2) ? (v + 1) : ((v == L) ? 0 : (v - 1));
                val = oth[w * DOTH + 27 + (i - 47)];
            }
        }
        s_scB[r * 58 + i] = dup2(val);
    }
    // ---- stage FV scalars (48) for output t = v-1 ----
    if (fvA) {
        for (int idx = j; idx < TTA * 48; idx += 256) {
            int r = idx / 48, i = idx - r * 48;
            int v = v0 + r;
            float val;
            if (i < 20)      val = oth[v * DOTH + 37 + i];
            else if (i < 30) val = oth[v * DOTH + 7 + i];          // 27 + (i-20)
            else if (i < 40) val = (v + 1 < MAXV) ? oth[(v + 1) * DOTH + (i - 3)] : 0.f;
            else             val = oth[v * DOTH + (i - 21)];       // 19 + (i-40)
            s_scV[r * 48 + i] = dup2(val);
        }
    }
    __syncthreads();
    dedup_codes(s_codes, s_codes2, j);
    __syncthreads();

    u64 aF[2][2], aB[2][2], a0[2][2];
    {
        ulonglong2 bvF = ldg4(bf + c0);
        ulonglong2 tvF = ldg4(&g_tgtF[b * HID + c0]);
        ulonglong2 bvB = ldg4(bb + c0);
        ulonglong2 tvB = ldg4(&g_tgtB[b * HID + c0]);
        u64 bF0 = f2add(bvF.x, tvF.x), bF1 = f2add(bvF.y, tvF.y);
        u64 bB0 = f2add(bvB.x, tvB.x), bB1 = f2add(bvB.y, tvB.y);
        u64 b00 = 0ull, b01 = 0ull;
        if (fvA) { ulonglong2 bv0 = ldg4(b0 + c0); b00 = bv0.x; b01 = bv0.y; }
        #pragma unroll
        for (int lr = 0; lr < 2; lr++) {
            aF[lr][0] = bF0; aF[lr][1] = bF1;
            aB[lr][0] = bB0; aB[lr][1] = bB1;
            a0[lr][0] = b00; a0[lr][1] = b01;
        }
    }

    // ---- merged gathers: one code read drives 3 (or 2) LDG.128 ----
    if (fvA) {
        #pragma unroll
        for (int lr = 0; lr < 2; lr++) {
            const int* cp = s_codes2 + (rbase + lr) * PP;
            u64 f0 = aF[lr][0], f1 = aF[lr][1];
            u64 k0 = aB[lr][0], k1 = aB[lr][1];
            u64 z0 = a0[lr][0], z1 = a0[lr][1];
            #pragma unroll 4
            for (int p = 0; p < PP; p++) {
                int c = cp[p];
                size_t off = (size_t)max(c, 0) * HID + c0;
                ulonglong2 wf = ldg4(Wf + off);
                ulonglong2 wb = ldg4(Wb + off);
                ulonglong2 w0 = ldg4(W0 + off);
                if (c >= 0) {
                    f0 = f2add(f0, wf.x); f1 = f2add(f1, wf.y);
                    k0 = f2add(k0, wb.x); k1 = f2add(k1, wb.y);
                    z0 = f2add(z0, w0.x); z1 = f2add(z1, w0.y);
                }
            }
            aF[lr][0] = f0; aF[lr][1] = f1;
            aB[lr][0] = k0; aB[lr][1] = k1;
            a0[lr][0] = z0; a0[lr][1] = z1;
        }
    } else {
        #pragma unroll
        for (int lr = 0; lr < 2; lr++) {
            const int* cp = s_codes2 + (rbase + lr) * PP;
            u64 f0 = aF[lr][0], f1 = aF[lr][1];
            u64 k0 = aB[lr][0], k1 = aB[lr][1];
            #pragma unroll 4
            for (int p = 0; p < PP; p++) {
                int c = cp[p];
                size_t off = (size_t)max(c, 0) * HID + c0;
                ulonglong2 wf = ldg4(Wf + off);
                ulonglong2 wb = ldg4(Wb + off);
                if (c >= 0) {
                    f0 = f2add(f0, wf.x); f1 = f2add(f1, wf.y);
                    k0 = f2add(k0, wb.x); k1 = f2add(k1, wb.y);
                }
            }
            aF[lr][0] = f0; aF[lr][1] = f1;
            aB[lr][0] = k0; aB[lr][1] = k1;
        }
    }

    // ---- dense parts ----
    dense_acc2(aF, s_scF, 58, 57, Wf, 607, rbase, c0);
    dense_acc2(aB, s_scB, 58, 57, Wb, 607, rbase, c0);
    if (fvA) dense_acc2(a0, s_scV, 48, 48, W0, 507, rbase, c0);

    // ---- stores ----
    #pragma unroll
    for (int lr = 0; lr < 2; lr++) {
        int v = v0 + rbase + lr;
        if (v < TOUT) {
            ulonglong2 o; o.x = aF[lr][0]; o.y = aF[lr][1];
            *reinterpret_cast<ulonglong2*>(&outF[((size_t)b * TOUT + v) * HID + c0]) = o;
        }
        int tb = (v < L) ? (L - 1 - v) : v;
        if (tb < TOUT) {
            ulonglong2 o; o.x = aB[lr][0]; o.y = aB[lr][1];
            *reinterpret_cast<ulonglong2*>(&outB[((size_t)b * TOUT + tb) * HID + c0]) = o;
        }
        if (fvA && v >= 1) {
            float x0, x1, x2, x3;
            unpack2(a0[lr][0], x0, x1);
            unpack2(a0[lr][1], x2, x3);
            ulonglong2 h0, h1v;
            h0.x  = dup2(fmaxf(x0, 0.f)); h0.y  = dup2(fmaxf(x1, 0.f));
            h1v.x = dup2(fmaxf(x2, 0.f)); h1v.y = dup2(fmaxf(x3, 0.f));
            u64* dst = &g_h1d[((size_t)b * MAXV + (v - 1)) * HID + c0];
            *reinterpret_cast<ulonglong2*>(dst)     = h0;
            *reinterpret_cast<ulonglong2*>(dst + 2) = h1v;
        }
    }
}

// ---------------------------------------------------------------------------
// Kernel C: W1 GEMM + L2 norm over t-tiles, reading h1 scratch.
// 128 col-pairs x 2 i-halves, all TTC rows register-resident.
// ---------------------------------------------------------------------------
__global__ __launch_bounds__(256, 5) void kernelC(
    const int* __restrict__ length,
    const float* __restrict__ W1, const float* __restrict__ b1,
    float* __restrict__ outV)
{
    __shared__ __align__(16) u64 s_h1d[TTC * HID];   // 20 KB; re-used as s_part
    __shared__ float s_red[4 * TTC];
    __shared__ float s_rsq[TTC];

    const int b  = blockIdx.y;
    const int t0 = blockIdx.x * TTC;
    const int j  = threadIdx.x;
    const int g2 = j >> 7;
    const int jc = j & 127;
    const int c2 = 2 * jc;
    const int L  = length[b];

    if (t0 < L - 2) {
        {
            const ulonglong2* src = reinterpret_cast<const ulonglong2*>(
                &g_h1d[((size_t)b * MAXV + t0) * HID]);
            ulonglong2* dst = reinterpret_cast<ulonglong2*>(s_h1d);
            #pragma unroll
            for (int k = 0; k < (TTC * HID / 2) / 256; k++)
                dst[j + k * 256] = src[j + k * 256];
        }
        __syncthreads();

        u64 acc2[TTC];
        {
            u64 init = (g2 == 0) ? ldg2(b1 + c2) : 0ull;
            #pragma unroll
            for (int r = 0; r < TTC; r++) acc2[r] = init;
        }
        {
            const float* Wp = W1 + (size_t)(g2 * 128) * HID + c2;
            const u64*   hp = s_h1d + g2 * 128;
            for (int i = 0; i < 128; i += 2) {
                u64 w0 = ldg2(Wp + (size_t)i * HID);
                u64 w1 = ldg2(Wp + (size_t)(i + 1) * HID);
                #pragma unroll
                for (int r = 0; r < TTC; r++) {
                    ulonglong2 hh = *reinterpret_cast<const ulonglong2*>(&hp[r * HID + i]);
                    acc2[r] = f2fma(hh.x, w0, acc2[r]);
                    acc2[r] = f2fma(hh.y, w1, acc2[r]);
                }
            }
        }
        __syncthreads();   // all reads of s_h1d done before aliasing as s_part
        u64* s_part = s_h1d;
        if (g2 == 1) {
            #pragma unroll
            for (int r = 0; r < TTC; r++) s_part[r * 128 + jc] = acc2[r];
        }
        __syncthreads();
        if (g2 == 0) {
            #pragma unroll
            for (int r = 0; r < TTC; r++) {
                acc2[r] = f2add(acc2[r], s_part[r * 128 + jc]);
                float x, y; unpack2(acc2[r], x, y);
                float v = x * x + y * y;
                v += __shfl_xor_sync(0xffffffffu, v, 16);
                v += __shfl_xor_sync(0xffffffffu, v, 8);
                v += __shfl_xor_sync(0xffffffffu, v, 4);
                v += __shfl_xor_sync(0xffffffffu, v, 2);
                v += __shfl_xor_sync(0xffffffffu, v, 1);
                if ((j & 31) == 0) s_red[(j >> 5) * TTC + r] = v;
            }
        }
        __syncthreads();
        if (j < TTC) {
            float s = 0.f;
            #pragma unroll
            for (int w = 0; w < 4; w++) s += s_red[w * TTC + j];
            float inv = rsqrtf(s);
            inv = inv * (1.5f - 0.5f * s * inv * inv);  // Newton step
            s_rsq[j] = inv;
        }
        __syncthreads();
        if (g2 == 0) {
            #pragma unroll
            for (int r = 0; r < TTC; r++) {
                int t = t0 + r;
                if (t < TOUT) {
                    float m = (t < L - 2) ? s_rsq[r] : 0.f;
                    float x, y; unpack2(acc2[r], x, y);
                    float2 o = make_float2(x * m, y * m);
                    *reinterpret_cast<float2*>(&outV[((size_t)b * TOUT + t) * HID + c2]) = o;
                }
            }
        }
    } else {
        for (int idx = j; idx < TTC * 128; idx += 256) {
            int r = idx >> 7, cc = idx & 127;
            int t = t0 + r;
            if (t < TOUT)
                *reinterpret_cast<u64*>(&outV[((size_t)b * TOUT + t) * HID + 2 * cc]) = 0ull;
        }
    }
}

// ---------------------------------------------------------------------------
extern "C" void kernel_launch(void* const* d_in, const int* in_sizes, int n_in,
                              void* d_out, int out_size)
{
    (void)in_sizes; (void)n_in; (void)out_size;
    const int*   code    = (const int*)  d_in[0];
    const float* others  = (const float*)d_in[1];
    const int*   length  = (const int*)  d_in[2];
    const int*   target  = (const int*)  d_in[3];
    const int*   widx    = (const int*)  d_in[4];
    const float* Wf      = (const float*)d_in[5];
    const float* bf      = (const float*)d_in[6];
    const float* Wb      = (const float*)d_in[7];
    const float* bb      = (const float*)d_in[8];
    const float* W0      = (const float*)d_in[9];
    const float* b0      = (const float*)d_in[10];
    const float* W1      = (const float*)d_in[11];
    const float* b1      = (const float*)d_in[12];

    float* outF = (float*)d_out;
    float* outB = outF + (size_t)BB * TOUT * HID;
    float* outV = outB + (size_t)BB * TOUT * HID;

    tgt_kernel<<<BB, 256>>>(target, widx, Wf, Wb);
    kernelA<<<dim3(NTA, BB), 256>>>(code, others, length,
                                    Wf, bf, Wb, bb, W0, b0, outF, outB);
    kernelC<<<dim3(NTC, BB), 256>>>(length, W1, b1, outV);
}

// round 14
// speedup vs baseline: 1.1178x; 1.1178x over previous
#include <cuda_runtime.h>

typedef unsigned long long u64;

// ---------------- problem constants ----------------
#define BB    64
#define MAXV  200
#define PP    40
#define DOTH  57
#define KK    100
#define TTA   8      // rows per block in kernel A (25 * 8 = 200 rows)
#define NTA   25
#define TTC   10     // t-steps per block in kernel C (20 * 10 = 200 >= 198)
#define NTC   20
#define TOUT  198
#define HID   256

// Per-batch tgt contributions (time-invariant)
__device__ float g_tgtF[BB * HID];
__device__ float g_tgtB[BB * HID];
// h1 scratch (duplicated f32x2 format): ~26 MB
__device__ u64 g_h1d[(size_t)BB * MAXV * HID];

// ---------------- packed f32x2 helpers ----------------
__device__ __forceinline__ u64 f2fma(u64 a, u64 b, u64 c) {
    u64 d; asm("fma.rn.f32x2 %0,%1,%2,%3;" : "=l"(d) : "l"(a), "l"(b), "l"(c)); return d;
}
__device__ __forceinline__ u64 f2add(u64 a, u64 b) {
    u64 d; asm("add.rn.f32x2 %0,%1,%2;" : "=l"(d) : "l"(a), "l"(b)); return d;
}
__device__ __forceinline__ u64 dup2(float v) {
    u64 d; asm("mov.b64 %0,{%1,%1};" : "=l"(d) : "f"(v)); return d;
}
__device__ __forceinline__ void unpack2(u64 v, float& x, float& y) {
    asm("mov.b64 {%0,%1},%2;" : "=f"(x), "=f"(y) : "l"(v));
}
__device__ __forceinline__ u64 ldg2(const float* __restrict__ p) {
    return *reinterpret_cast<const u64*>(p);
}

// ---------------------------------------------------------------------------
// Kernel 1: per-batch tgt @ Wf[507:607] / Wb[507:607].
// Multiply-form (kf in {0,1}), 1024 threads: (col-pair, matrix, k-quarter).
// Each thread sums 25 codes; deterministic smem combine of the 4 quarters.
// ---------------------------------------------------------------------------
__global__ __launch_bounds__(1024) void tgt_kernel(
    const int* __restrict__ target, const int* __restrict__ widx,
    const float* __restrict__ Wf, const float* __restrict__ Wb)
{
    __shared__ int s_t[10];
    __shared__ u64 s_kf2[KK];      // keep flag duplicated as f32x2
    __shared__ u64 s_part[1024];
    const int b = blockIdx.x;
    const int j = threadIdx.x;
    if (j < 10) s_t[j] = target[b * 10 + j];
    __syncthreads();
    if (j < KK) {
        int w = widx[j];
        int keep = 1;
        #pragma unroll
        for (int q = 0; q < 10; q++) keep &= (s_t[q] != w);
        s_kf2[j] = dup2(keep ? 1.f : 0.f);
    }
    __syncthreads();
    const int pair = j & 127;           // col-pair
    const int m    = (j >> 7) & 1;      // 0 = Wf, 1 = Wb
    const int kq   = j >> 8;            // k-quarter
    const int c0   = 2 * pair;
    const float* W = m ? Wb : Wf;
    u64 a = 0ull;
    const int k0 = kq * 25;
    #pragma unroll
    for (int k = 0; k < 25; k++)
        a = f2fma(s_kf2[k0 + k], ldg2(W + (size_t)(507 + k0 + k) * HID + c0), a);
    s_part[j] = a;
    __syncthreads();
    if (kq == 0) {
        // deterministic order: q0 + q1 + q2 + q3
        u64 t = f2add(f2add(a, s_part[j + 256]),
                      f2add(s_part[j + 512], s_part[j + 768]));
        float* dst = m ? g_tgtB : g_tgtF;
        *reinterpret_cast<u64*>(&dst[b * HID + c0]) = t;
    }
}

// ---------------------------------------------------------------------------
// Dedup within each row of PP codes (multi_hot duplicate collapse). -1 = skip.
// ---------------------------------------------------------------------------
__device__ __forceinline__ void dedup_codes(const int* __restrict__ s_codes,
                                            int* __restrict__ s_out, int j)
{
    for (int idx = j; idx < TTA * PP; idx += 256) {
        int p = idx % PP;
        int base = idx - p;
        int c = s_codes[idx];
        int take = 1;
        for (int q = 0; q < p; q++) take &= (s_codes[base + q] != c);
        s_out[idx] = take ? c : -1;
    }
}

// ---------------------------------------------------------------------------
// Dense feature accumulate: 4 rows, f32x2-packed, ull2 scalar pair reads.
// ---------------------------------------------------------------------------
__device__ __forceinline__ void dense_acc(
    u64* __restrict__ acc, const u64* __restrict__ sc, int stride, int nd,
    const float* __restrict__ W, int row0, int rbase, int c0)
{
    int i = 0;
    for (; i + 1 < nd; i += 2) {
        u64 w0 = ldg2(W + (size_t)(row0 + i) * HID + c0);
        u64 w1 = ldg2(W + (size_t)(row0 + i + 1) * HID + c0);
        #pragma unroll
        for (int lr = 0; lr < 4; lr++) {
            ulonglong2 s = *reinterpret_cast<const ulonglong2*>(&sc[(rbase + lr) * stride + i]);
            acc[lr] = f2fma(s.x, w0, acc[lr]);
            acc[lr] = f2fma(s.y, w1, acc[lr]);
        }
    }
    if (i < nd) {
        u64 w0 = ldg2(W + (size_t)(row0 + i) * HID + c0);
        #pragma unroll
        for (int lr = 0; lr < 4; lr++)
            acc[lr] = f2fma(sc[(rbase + lr) * stride + i], w0, acc[lr]);
    }
}

// ---------------------------------------------------------------------------
// Kernel A: unified per-row gathers (R12 configuration: 128 col-pairs x
// 2 row-groups of 4 rows). One code stage + one dedup drives Wf/Wb/W0
// gathers simultaneously. outF[t=v], outB scattered to t_b(v), h1 -> scratch.
// ---------------------------------------------------------------------------
__global__ __launch_bounds__(256, 5) void kernelA(
    const int*   __restrict__ code,   const float* __restrict__ others,
    const int*   __restrict__ length,
    const float* __restrict__ Wf, const float* __restrict__ bf,
    const float* __restrict__ Wb, const float* __restrict__ bb,
    const float* __restrict__ W0, const float* __restrict__ b0,
    float* __restrict__ outF, float* __restrict__ outB)
{
    __shared__ int s_codes[TTA * PP];
    __shared__ int s_codes2[TTA * PP];
    __shared__ __align__(16) u64 s_scF[TTA * 58];
    __shared__ __align__(16) u64 s_scB[TTA * 58];
    __shared__ __align__(16) u64 s_scV[TTA * 48];

    const int b  = blockIdx.y;
    const int v0 = blockIdx.x * TTA;
    const int j  = threadIdx.x;
    const int jc = j & 127;
    const int g  = j >> 7;
    const int c0 = 2 * jc;
    const int rbase = g * 4;
    const int L  = length[b];
    const bool fvA = (v0 <= L - 2);   // any row v in block has v <= L-2

    const float* oth = others + (size_t)b * MAXV * DOTH;
    const int*   cod = code   + (size_t)b * MAXV * PP;

    // ---- stage codes ----
    for (int idx = j; idx < TTA * PP; idx += 256) {
        int r = idx / PP, p = idx - r * PP;
        s_codes[idx] = cod[(v0 + r) * PP + p];
    }
    // ---- stage forward scalars (57) ----
    for (int idx = j; idx < TTA * 57; idx += 256) {
        int r = idx / 57, i = idx - r * 57;
        int col = (i < 27) ? i : ((i < 47) ? i + 10 : i - 20);
        s_scF[r * 58 + i] = dup2(oth[(v0 + r) * DOTH + col]);
    }
    // ---- stage backward scalars (57): cols 0..46 = feature(v), 47..56 = interval(w(v)) ----
    for (int idx = j; idx < TTA * 57; idx += 256) {
        int r = idx / 57, i = idx - r * 57;
        int v = v0 + r;
        float val;
        if (i < 47) {
            int col = (i < 27) ? i : i + 10;
            val = oth[v * DOTH + col];
        } else {
            if (v == L - 1) val = 0.f;
            else {
                int w = (v <= L - 2) ? (v + 1) : ((v == L) ? 0 : (v - 1));
                val = oth[w * DOTH + 27 + (i - 47)];
            }
        }
        s_scB[r * 58 + i] = dup2(val);
    }
    // ---- stage FV scalars (48) for output t = v-1 ----
    if (fvA) {
        for (int idx = j; idx < TTA * 48; idx += 256) {
            int r = idx / 48, i = idx - r * 48;
            int v = v0 + r;
            float val;
            if (i < 20)      val = oth[v * DOTH + 37 + i];
            else if (i < 30) val = oth[v * DOTH + 7 + i];         // 27 + (i-20)
            else if (i < 40) val = (v + 1 < MAXV) ? oth[(v + 1) * DOTH + (i - 3)] : 0.f; // 27+(i-30)
            else             val = oth[v * DOTH + (i - 21)];      // 19 + (i-40)
            s_scV[r * 48 + i] = dup2(val);
        }
    }
    __syncthreads();
    dedup_codes(s_codes, s_codes2, j);
    __syncthreads();

    u64 aF[4], aB[4], a0[4];
    {
        u64 baseF = f2add(ldg2(bf + c0), ldg2(&g_tgtF[b * HID + c0]));
        u64 baseB = f2add(ldg2(bb + c0), ldg2(&g_tgtB[b * HID + c0]));
        u64 base0 = fvA ? ldg2(b0 + c0) : 0ull;
        #pragma unroll
        for (int lr = 0; lr < 4; lr++) { aF[lr] = baseF; aB[lr] = baseB; a0[lr] = base0; }
    }

    // ---- merged gathers: one code read drives 3 (or 2) weight loads ----
    if (fvA) {
        #pragma unroll
        for (int lr = 0; lr < 4; lr++) {
            const int* cp = s_codes2 + (rbase + lr) * PP;
            u64 f = aF[lr], bk = aB[lr], z = a0[lr];
            #pragma unroll 4
            for (int p = 0; p < PP; p++) {
                int c = cp[p];
                int cc = max(c, 0);
                u64 wf = ldg2(Wf + (size_t)cc * HID + c0);
                u64 wb = ldg2(Wb + (size_t)cc * HID + c0);
                u64 w0 = ldg2(W0 + (size_t)cc * HID + c0);
                if (c >= 0) { f = f2add(f, wf); bk = f2add(bk, wb); z = f2add(z, w0); }
            }
            aF[lr] = f; aB[lr] = bk; a0[lr] = z;
        }
    } else {
        #pragma unroll
        for (int lr = 0; lr < 4; lr++) {
            const int* cp = s_codes2 + (rbase + lr) * PP;
            u64 f = aF[lr], bk = aB[lr];
            #pragma unroll 4
            for (int p = 0; p < PP; p++) {
                int c = cp[p];
                int cc = max(c, 0);
                u64 wf = ldg2(Wf + (size_t)cc * HID + c0);
                u64 wb = ldg2(Wb + (size_t)cc * HID + c0);
                if (c >= 0) { f = f2add(f, wf); bk = f2add(bk, wb); }
            }
            aF[lr] = f; aB[lr] = bk;
        }
    }

    // ---- dense parts ----
    dense_acc(aF, s_scF, 58, 57, Wf, 607, rbase, c0);
    dense_acc(aB, s_scB, 58, 57, Wb, 607, rbase, c0);
    if (fvA) dense_acc(a0, s_scV, 48, 48, W0, 507, rbase, c0);

    // ---- stores ----
    #pragma unroll
    for (int lr = 0; lr < 4; lr++) {
        int v = v0 + rbase + lr;
        if (v < TOUT)
            *reinterpret_cast<u64*>(&outF[((size_t)b * TOUT + v) * HID + c0]) = aF[lr];
        int tb = (v < L) ? (L - 1 - v) : v;
        if (tb < TOUT)
            *reinterpret_cast<u64*>(&outB[((size_t)b * TOUT + tb) * HID + c0]) = aB[lr];
        if (fvA && v >= 1) {
            float x, y; unpack2(a0[lr], x, y);
            ulonglong2 hv;
            hv.x = dup2(fmaxf(x, 0.f));
            hv.y = dup2(fmaxf(y, 0.f));
            *reinterpret_cast<ulonglong2*>(&g_h1d[((size_t)b * MAXV + (v - 1)) * HID + c0]) = hv;
        }
    }
}

// ---------------------------------------------------------------------------
// Kernel C: W1 GEMM + L2 norm over t-tiles, reading h1 scratch.
// 128 col-pairs x 2 i-halves, all TTC rows register-resident.
// ---------------------------------------------------------------------------
__global__ __launch_bounds__(256, 5) void kernelC(
    const int* __restrict__ length,
    const float* __restrict__ W1, const float* __restrict__ b1,
    float* __restrict__ outV)
{
    __shared__ __align__(16) u64 s_h1d[TTC * HID];   // 20 KB; re-used as s_part
    __shared__ float s_red[4 * TTC];
    __shared__ float s_rsq[TTC];

    const int b  = blockIdx.y;
    const int t0 = blockIdx.x * TTC;
    const int j  = threadIdx.x;
    const int g2 = j >> 7;
    const int jc = j & 127;
    const int c2 = 2 * jc;
    const int L  = length[b];

    if (t0 < L - 2) {
        {
            const ulonglong2* src = reinterpret_cast<const ulonglong2*>(
                &g_h1d[((size_t)b * MAXV + t0) * HID]);
            ulonglong2* dst = reinterpret_cast<ulonglong2*>(s_h1d);
            #pragma unroll
            for (int k = 0; k < (TTC * HID / 2) / 256; k++)
                dst[j + k * 256] = src[j + k * 256];
        }
        __syncthreads();

        u64 acc2[TTC];
        {
            u64 init = (g2 == 0) ? ldg2(b1 + c2) : 0ull;
            #pragma unroll
            for (int r = 0; r < TTC; r++) acc2[r] = init;
        }
        {
            const float* Wp = W1 + (size_t)(g2 * 128) * HID + c2;
            const u64*   hp = s_h1d + g2 * 128;
            for (int i = 0; i < 128; i += 2) {
                u64 w0 = ldg2(Wp + (size_t)i * HID);
                u64 w1 = ldg2(Wp + (size_t)(i + 1) * HID);
                #pragma unroll
                for (int r = 0; r < TTC; r++) {
                    ulonglong2 hh = *reinterpret_cast<const ulonglong2*>(&hp[r * HID + i]);
                    acc2[r] = f2fma(hh.x, w0, acc2[r]);
                    acc2[r] = f2fma(hh.y, w1, acc2[r]);
                }
            }
        }
        __syncthreads();   // all reads of s_h1d done before aliasing as s_part
        u64* s_part = s_h1d;
        if (g2 == 1) {
            #pragma unroll
            for (int r = 0; r < TTC; r++) s_part[r * 128 + jc] = acc2[r];
        }
        __syncthreads();
        if (g2 == 0) {
            #pragma unroll
            for (int r = 0; r < TTC; r++) {
                acc2[r] = f2add(acc2[r], s_part[r * 128 + jc]);
                float x, y; unpack2(acc2[r], x, y);
                float v = x * x + y * y;
                v += __shfl_xor_sync(0xffffffffu, v, 16);
                v += __shfl_xor_sync(0xffffffffu, v, 8);
                v += __shfl_xor_sync(0xffffffffu, v, 4);
                v += __shfl_xor_sync(0xffffffffu, v, 2);
                v += __shfl_xor_sync(0xffffffffu, v, 1);
                if ((j & 31) == 0) s_red[(j >> 5) * TTC + r] = v;
            }
        }
        __syncthreads();
        if (j < TTC) {
            float s = 0.f;
            #pragma unroll
            for (int w = 0; w < 4; w++) s += s_red[w * TTC + j];
            float inv = rsqrtf(s);
            inv = inv * (1.5f - 0.5f * s * inv * inv);  // Newton step
            s_rsq[j] = inv;
        }
        __syncthreads();
        if (g2 == 0) {
            #pragma unroll
            for (int r = 0; r < TTC; r++) {
                int t = t0 + r;
                if (t < TOUT) {
                    float m = (t < L - 2) ? s_rsq[r] : 0.f;
                    float x, y; unpack2(acc2[r], x, y);
                    float2 o = make_float2(x * m, y * m);
                    *reinterpret_cast<float2*>(&outV[((size_t)b * TOUT + t) * HID + c2]) = o;
                }
            }
        }
    } else {
        for (int idx = j; idx < TTC * 128; idx += 256) {
            int r = idx >> 7, cc = idx & 127;
            int t = t0 + r;
            if (t < TOUT)
                *reinterpret_cast<u64*>(&outV[((size_t)b * TOUT + t) * HID + 2 * cc]) = 0ull;
        }
    }
}

// ---------------------------------------------------------------------------
extern "C" void kernel_launch(void* const* d_in, const int* in_sizes, int n_in,
                              void* d_out, int out_size)
{
    (void)in_sizes; (void)n_in; (void)out_size;
    const int*   code    = (const int*)  d_in[0];
    const float* others  = (const float*)d_in[1];
    const int*   length  = (const int*)  d_in[2];
    const int*   target  = (const int*)  d_in[3];
    const int*   widx    = (const int*)  d_in[4];
    const float* Wf      = (const float*)d_in[5];
    const float* bf      = (const float*)d_in[6];
    const float* Wb      = (const float*)d_in[7];
    const float* bb      = (const float*)d_in[8];
    const float* W0      = (const float*)d_in[9];
    const float* b0      = (const float*)d_in[10];
    const float* W1      = (const float*)d_in[11];
    const float* b1      = (const float*)d_in[12];

    float* outF = (float*)d_out;
    float* outB = outF + (size_t)BB * TOUT * HID;
    float* outV = outB + (size_t)BB * TOUT * HID;

    tgt_kernel<<<BB, 1024>>>(target, widx, Wf, Wb);
    kernelA<<<dim3(NTA, BB), 256>>>(code, others, length,
                                    Wf, bf, Wb, bb, W0, b0, outF, outB);
    kernelC<<<dim3(NTC, BB), 256>>>(length, W1, b1, outV);
}

// round 16
// speedup vs baseline: 1.1581x; 1.0361x over previous
#include <cuda_runtime.h>

typedef unsigned long long u64;

// ---------------- problem constants ----------------
#define BB    64
#define MAXV  200
#define PP    40
#define DOTH  57
#define KK    100
#define TTA   8      // rows per block in kernel A (25 * 8 = 200 rows)
#define NTA   25
#define TTC   8      // t-steps per block in kernel C (25 * 8 = 200 >= 198)
#define NTC   25
#define TOUT  198
#define HID   256

// Per-batch tgt contributions (time-invariant)
__device__ float g_tgtF[BB * HID];
__device__ float g_tgtB[BB * HID];
// h1 scratch (duplicated f32x2 format): ~26 MB
__device__ u64 g_h1d[(size_t)BB * MAXV * HID];

// ---------------- packed f32x2 helpers ----------------
__device__ __forceinline__ u64 f2fma(u64 a, u64 b, u64 c) {
    u64 d; asm("fma.rn.f32x2 %0,%1,%2,%3;" : "=l"(d) : "l"(a), "l"(b), "l"(c)); return d;
}
__device__ __forceinline__ u64 f2add(u64 a, u64 b) {
    u64 d; asm("add.rn.f32x2 %0,%1,%2;" : "=l"(d) : "l"(a), "l"(b)); return d;
}
__device__ __forceinline__ u64 dup2(float v) {
    u64 d; asm("mov.b64 %0,{%1,%1};" : "=l"(d) : "f"(v)); return d;
}
__device__ __forceinline__ void unpack2(u64 v, float& x, float& y) {
    asm("mov.b64 {%0,%1},%2;" : "=f"(x), "=f"(y) : "l"(v));
}
__device__ __forceinline__ u64 ldg2(const float* __restrict__ p) {
    return *reinterpret_cast<const u64*>(p);
}
__device__ __forceinline__ ulonglong2 ldg4(const float* __restrict__ p) {
    return *reinterpret_cast<const ulonglong2*>(p);
}

// ---------------------------------------------------------------------------
// Kernel 1: per-batch tgt @ Wf[507:607] / Wb[507:607].
// Multiply-form (kf in {0,1}), 1024 threads: (col-pair, matrix, k-quarter).
// ---------------------------------------------------------------------------
__global__ __launch_bounds__(1024) void tgt_kernel(
    const int* __restrict__ target, const int* __restrict__ widx,
    const float* __restrict__ Wf, const float* __restrict__ Wb)
{
    __shared__ int s_t[10];
    __shared__ u64 s_kf2[KK];
    __shared__ u64 s_part[1024];
    const int b = blockIdx.x;
    const int j = threadIdx.x;
    if (j < 10) s_t[j] = target[b * 10 + j];
    __syncthreads();
    if (j < KK) {
        int w = widx[j];
        int keep = 1;
        #pragma unroll
        for (int q = 0; q < 10; q++) keep &= (s_t[q] != w);
        s_kf2[j] = dup2(keep ? 1.f : 0.f);
    }
    __syncthreads();
    const int pair = j & 127;
    const int m    = (j >> 7) & 1;
    const int kq   = j >> 8;
    const int c0   = 2 * pair;
    const float* W = m ? Wb : Wf;
    u64 a = 0ull;
    const int k0 = kq * 25;
    #pragma unroll
    for (int k = 0; k < 25; k++)
        a = f2fma(s_kf2[k0 + k], ldg2(W + (size_t)(507 + k0 + k) * HID + c0), a);
    s_part[j] = a;
    __syncthreads();
    if (kq == 0) {
        u64 t = f2add(f2add(a, s_part[j + 256]),
                      f2add(s_part[j + 512], s_part[j + 768]));
        float* dst = m ? g_tgtB : g_tgtF;
        *reinterpret_cast<u64*>(&dst[b * HID + c0]) = t;
    }
}

// ---------------------------------------------------------------------------
// Dedup within each row of PP codes (multi_hot duplicate collapse). -1 = skip.
// ---------------------------------------------------------------------------
__device__ __forceinline__ void dedup_codes(const int* __restrict__ s_codes,
                                            int* __restrict__ s_out, int j)
{
    for (int idx = j; idx < TTA * PP; idx += 256) {
        int p = idx % PP;
        int base = idx - p;
        int c = s_codes[idx];
        int take = 1;
        for (int q = 0; q < p; q++) take &= (s_codes[base + q] != c);
        s_out[idx] = take ? c : -1;
    }
}

// ---------------------------------------------------------------------------
// Dense feature accumulate: 4 rows, f32x2-packed (used by FV / W0 path).
// ---------------------------------------------------------------------------
__device__ __forceinline__ void dense_acc(
    u64* __restrict__ acc, const u64* __restrict__ sc, int stride, int nd,
    const float* __restrict__ W, int row0, int rbase, int c0)
{
    int i = 0;
    for (; i + 1 < nd; i += 2) {
        u64 w0 = ldg2(W + (size_t)(row0 + i) * HID + c0);
        u64 w1 = ldg2(W + (size_t)(row0 + i + 1) * HID + c0);
        #pragma unroll
        for (int lr = 0; lr < 4; lr++) {
            ulonglong2 s = *reinterpret_cast<const ulonglong2*>(&sc[(rbase + lr) * stride + i]);
            acc[lr] = f2fma(s.x, w0, acc[lr]);
            acc[lr] = f2fma(s.y, w1, acc[lr]);
        }
    }
    if (i < nd) {
        u64 w0 = ldg2(W + (size_t)(row0 + i) * HID + c0);
        #pragma unroll
        for (int lr = 0; lr < 4; lr++)
            acc[lr] = f2fma(sc[(rbase + lr) * stride + i], w0, acc[lr]);
    }
}

// ---------------------------------------------------------------------------
// Kernel A: unified per-row gathers (128 col-pairs x 2 row-groups of 4 rows).
// One code stage + one dedup drives Wf/Wb/W0 gathers. Forward/backward dense
// feature passes MERGED over the 47 shared feature columns.
// ---------------------------------------------------------------------------
__global__ __launch_bounds__(256, 5) void kernelA(
    const int*   __restrict__ code,   const float* __restrict__ others,
    const int*   __restrict__ length,
    const float* __restrict__ Wf, const float* __restrict__ bf,
    const float* __restrict__ Wb, const float* __restrict__ bb,
    const float* __restrict__ W0, const float* __restrict__ b0,
    float* __restrict__ outF, float* __restrict__ outB)
{
    __shared__ int s_codes[TTA * PP];
    __shared__ int s_codes2[TTA * PP];
    __shared__ __align__(16) u64 s_scF[TTA * 58];   // cols 0..46 feat, 48..57 fwd interval
    __shared__ __align__(16) u64 s_scB[TTA * 12];   // 10 backward interval cols
    __shared__ __align__(16) u64 s_scV[TTA * 48];

    const int b  = blockIdx.y;
    const int v0 = blockIdx.x * TTA;
    const int j  = threadIdx.x;
    const int jc = j & 127;
    const int g  = j >> 7;
    const int c0 = 2 * jc;
    const int rbase = g * 4;
    const int L  = length[b];
    const bool fvA = (v0 <= L - 2);

    const float* oth = others + (size_t)b * MAXV * DOTH;
    const int*   cod = code   + (size_t)b * MAXV * PP;

    // ---- stage codes ----
    for (int idx = j; idx < TTA * PP; idx += 256) {
        int r = idx / PP, p = idx - r * PP;
        s_codes[idx] = cod[(v0 + r) * PP + p];
    }
    // ---- stage forward scalars: 47 feature cols at 0..46, interval at 48..57 ----
    for (int idx = j; idx < TTA * 57; idx += 256) {
        int r = idx / 57, i = idx - r * 57;
        int col, pos;
        if (i < 27)      { col = i;      pos = i; }
        else if (i < 47) { col = i + 10; pos = i; }
        else             { col = i - 20; pos = i + 1; }   // 48..57
        s_scF[r * 58 + pos] = dup2(oth[(v0 + r) * DOTH + col]);
    }
    // ---- stage backward interval scalars (10 cols) ----
    for (int idx = j; idx < TTA * 10; idx += 256) {
        int r = idx / 10, i = idx - r * 10;
        int v = v0 + r;
        float val;
        if (v == L - 1) val = 0.f;
        else {
            int w = (v <= L - 2) ? (v + 1) : ((v == L) ? 0 : (v - 1));
            val = oth[w * DOTH + 27 + i];
        }
        s_scB[r * 12 + i] = dup2(val);
    }
    // ---- stage FV scalars (48) for output t = v-1 ----
    if (fvA) {
        for (int idx = j; idx < TTA * 48; idx += 256) {
            int r = idx / 48, i = idx - r * 48;
            int v = v0 + r;
            float val;
            if (i < 20)      val = oth[v * DOTH + 37 + i];
            else if (i < 30) val = oth[v * DOTH + 7 + i];
            else if (i < 40) val = (v + 1 < MAXV) ? oth[(v + 1) * DOTH + (i - 3)] : 0.f;
            else             val = oth[v * DOTH + (i - 21)];
            s_scV[r * 48 + i] = dup2(val);
        }
    }
    __syncthreads();
    dedup_codes(s_codes, s_codes2, j);
    __syncthreads();

    u64 aF[4], aB[4], a0[4];
    {
        u64 baseF = f2add(ldg2(bf + c0), ldg2(&g_tgtF[b * HID + c0]));
        u64 baseB = f2add(ldg2(bb + c0), ldg2(&g_tgtB[b * HID + c0]));
        u64 base0 = fvA ? ldg2(b0 + c0) : 0ull;
        #pragma unroll
        for (int lr = 0; lr < 4; lr++) { aF[lr] = baseF; aB[lr] = baseB; a0[lr] = base0; }
    }

    // ---- merged gathers: one code read drives 3 (or 2) weight loads ----
    if (fvA) {
        #pragma unroll
        for (int lr = 0; lr < 4; lr++) {
            const int* cp = s_codes2 + (rbase + lr) * PP;
            u64 f = aF[lr], bk = aB[lr], z = a0[lr];
            #pragma unroll 4
            for (int p = 0; p < PP; p++) {
                int c = cp[p];
                int cc = max(c, 0);
                u64 wf = ldg2(Wf + (size_t)cc * HID + c0);
                u64 wb = ldg2(Wb + (size_t)cc * HID + c0);
                u64 w0 = ldg2(W0 + (size_t)cc * HID + c0);
                if (c >= 0) { f = f2add(f, wf); bk = f2add(bk, wb); z = f2add(z, w0); }
            }
            aF[lr] = f; aB[lr] = bk; a0[lr] = z;
        }
    } else {
        #pragma unroll
        for (int lr = 0; lr < 4; lr++) {
            const int* cp = s_codes2 + (rbase + lr) * PP;
            u64 f = aF[lr], bk = aB[lr];
            #pragma unroll 4
            for (int p = 0; p < PP; p++) {
                int c = cp[p];
                int cc = max(c, 0);
                u64 wf = ldg2(Wf + (size_t)cc * HID + c0);
                u64 wb = ldg2(Wb + (size_t)cc * HID + c0);
                if (c >= 0) { f = f2add(f, wf); bk = f2add(bk, wb); }
            }
            aF[lr] = f; aB[lr] = bk;
        }
    }

    // ---- MERGED dense features (47 shared cols, rows 607..653 of Wf AND Wb) ----
    {
        int i = 0;
        for (; i + 1 < 47; i += 2) {
            u64 wf0 = ldg2(Wf + (size_t)(607 + i) * HID + c0);
            u64 wf1 = ldg2(Wf + (size_t)(608 + i) * HID + c0);
            u64 wb0 = ldg2(Wb + (size_t)(607 + i) * HID + c0);
            u64 wb1 = ldg2(Wb + (size_t)(608 + i) * HID + c0);
            #pragma unroll
            for (int lr = 0; lr < 4; lr++) {
                ulonglong2 s = *reinterpret_cast<const ulonglong2*>(&s_scF[(rbase + lr) * 58 + i]);
                aF[lr] = f2fma(s.x, wf0, aF[lr]);
                aF[lr] = f2fma(s.y, wf1, aF[lr]);
                aB[lr] = f2fma(s.x, wb0, aB[lr]);
                aB[lr] = f2fma(s.y, wb1, aB[lr]);
            }
        }
        // remainder col 46 (row 653)
        u64 wf = ldg2(Wf + (size_t)653 * HID + c0);
        u64 wb = ldg2(Wb + (size_t)653 * HID + c0);
        #pragma unroll
        for (int lr = 0; lr < 4; lr++) {
            u64 s = s_scF[(rbase + lr) * 58 + 46];
            aF[lr] = f2fma(s, wf, aF[lr]);
            aB[lr] = f2fma(s, wb, aB[lr]);
        }
    }
    // ---- forward interval (10 cols at s_scF 48..57, rows 654..663) ----
    #pragma unroll
    for (int i = 0; i < 10; i += 2) {
        u64 w0 = ldg2(Wf + (size_t)(654 + i) * HID + c0);
        u64 w1 = ldg2(Wf + (size_t)(655 + i) * HID + c0);
        #pragma unroll
        for (int lr = 0; lr < 4; lr++) {
            ulonglong2 s = *reinterpret_cast<const ulonglong2*>(&s_scF[(rbase + lr) * 58 + 48 + i]);
            aF[lr] = f2fma(s.x, w0, aF[lr]);
            aF[lr] = f2fma(s.y, w1, aF[lr]);
        }
    }
    // ---- backward interval (10 cols, rows 654..663) ----
    #pragma unroll
    for (int i = 0; i < 10; i += 2) {
        u64 w0 = ldg2(Wb + (size_t)(654 + i) * HID + c0);
        u64 w1 = ldg2(Wb + (size_t)(655 + i) * HID + c0);
        #pragma unroll
        for (int lr = 0; lr < 4; lr++) {
            ulonglong2 s = *reinterpret_cast<const ulonglong2*>(&s_scB[(rbase + lr) * 12 + i]);
            aB[lr] = f2fma(s.x, w0, aB[lr]);
            aB[lr] = f2fma(s.y, w1, aB[lr]);
        }
    }
    // ---- FV dense ----
    if (fvA) dense_acc(a0, s_scV, 48, 48, W0, 507, rbase, c0);

    // ---- stores ----
    #pragma unroll
    for (int lr = 0; lr < 4; lr++) {
        int v = v0 + rbase + lr;
        if (v < TOUT)
            *reinterpret_cast<u64*>(&outF[((size_t)b * TOUT + v) * HID + c0]) = aF[lr];
        int tb = (v < L) ? (L - 1 - v) : v;
        if (tb < TOUT)
            *reinterpret_cast<u64*>(&outB[((size_t)b * TOUT + tb) * HID + c0]) = aB[lr];
        if (fvA && v >= 1) {
            float x, y; unpack2(a0[lr], x, y);
            ulonglong2 hv;
            hv.x = dup2(fmaxf(x, 0.f));
            hv.y = dup2(fmaxf(y, 0.f));
            *reinterpret_cast<ulonglong2*>(&g_h1d[((size_t)b * MAXV + (v - 1)) * HID + c0]) = hv;
        }
    }
}

// ---------------------------------------------------------------------------
// Kernel C: W1 GEMM + L2 norm. Thread = (col-quad cq of 4 cols, K-segment ks
// of 64). All TTC=8 rows register-resident (16 u64 accs). Per-thread K-range
// halved vs R12 -> smem wavefronts halved. Deterministic 4-segment combine.
// ---------------------------------------------------------------------------
__global__ __launch_bounds__(256, 4) void kernelC(
    const int* __restrict__ length,
    const float* __restrict__ W1, const float* __restrict__ b1,
    float* __restrict__ outV)
{
    __shared__ __align__(16) u64 s_h1d[TTC * HID];      // 16 KB
    __shared__ __align__(16) u64 s_part[3 * 64 * 16];   // 24 KB
    __shared__ float s_red[2 * TTC];
    __shared__ float s_rsq[TTC];

    const int b  = blockIdx.y;
    const int t0 = blockIdx.x * TTC;
    const int j  = threadIdx.x;
    const int cq = j & 63;
    const int ks = j >> 6;
    const int c0 = cq * 4;
    const int L  = length[b];

    if (t0 < L - 2) {
        // load h1 tile (duplicated format): 1024 ull2, 4 per thread
        {
            const ulonglong2* src = reinterpret_cast<const ulonglong2*>(
                &g_h1d[((size_t)b * MAXV + t0) * HID]);
            ulonglong2* dst = reinterpret_cast<ulonglong2*>(s_h1d);
            #pragma unroll
            for (int k = 0; k < 4; k++)
                dst[j + k * 256] = src[j + k * 256];
        }
        __syncthreads();

        u64 acc[TTC][2];
        {
            ulonglong2 init; init.x = 0ull; init.y = 0ull;
            if (ks == 0) init = ldg4(b1 + c0);
            #pragma unroll
            for (int r = 0; r < TTC; r++) { acc[r][0] = init.x; acc[r][1] = init.y; }
        }
        {
            const int i0 = ks * 64;
            const float* Wp = W1 + (size_t)i0 * HID + c0;
            const u64*   hp = s_h1d + i0;
            for (int i = 0; i < 64; i += 2) {
                ulonglong2 w0 = ldg4(Wp + (size_t)i * HID);
                ulonglong2 w1 = ldg4(Wp + (size_t)(i + 1) * HID);
                #pragma unroll
                for (int r = 0; r < TTC; r++) {
                    ulonglong2 h = *reinterpret_cast<const ulonglong2*>(&hp[r * HID + i]);
                    acc[r][0] = f2fma(h.x, w0.x, acc[r][0]);
                    acc[r][1] = f2fma(h.x, w0.y, acc[r][1]);
                    acc[r][0] = f2fma(h.y, w1.x, acc[r][0]);
                    acc[r][1] = f2fma(h.y, w1.y, acc[r][1]);
                }
            }
        }
        __syncthreads();
        if (ks > 0) {
            u64* dst = &s_part[((ks - 1) * 64 + cq) * 16];
            #pragma unroll
            for (int r = 0; r < TTC; r++) {
                dst[r * 2]     = acc[r][0];
                dst[r * 2 + 1] = acc[r][1];
            }
        }
        __syncthreads();
        if (ks == 0) {
            // deterministic: seg0 + seg1 + seg2 + seg3
            #pragma unroll
            for (int seg = 0; seg < 3; seg++) {
                const u64* src = &s_part[(seg * 64 + cq) * 16];
                #pragma unroll
                for (int r = 0; r < TTC; r++) {
                    acc[r][0] = f2add(acc[r][0], src[r * 2]);
                    acc[r][1] = f2add(acc[r][1], src[r * 2 + 1]);
                }
            }
            #pragma unroll
            for (int r = 0; r < TTC; r++) {
                float x0, x1, x2, x3;
                unpack2(acc[r][0], x0, x1);
                unpack2(acc[r][1], x2, x3);
                float v = x0 * x0 + x1 * x1 + x2 * x2 + x3 * x3;
                v += __shfl_xor_sync(0xffffffffu, v, 16);
                v += __shfl_xor_sync(0xffffffffu, v, 8);
                v += __shfl_xor_sync(0xffffffffu, v, 4);
                v += __shfl_xor_sync(0xffffffffu, v, 2);
                v += __shfl_xor_sync(0xffffffffu, v, 1);
                if ((j & 31) == 0) s_red[(j >> 5) * TTC + r] = v;
            }
        }
        __syncthreads();
        if (j < TTC) {
            float s = s_red[j] + s_red[TTC + j];
            float inv = rsqrtf(s);
            inv = inv * (1.5f - 0.5f * s * inv * inv);  // Newton step
            s_rsq[j] = inv;
        }
        __syncthreads();
        if (ks == 0) {
            #pragma unroll
            for (int r = 0; r < TTC; r++) {
                int t = t0 + r;
                if (t < TOUT) {
                    float m = (t < L - 2) ? s_rsq[r] : 0.f;
                    float x0, x1, x2, x3;
                    unpack2(acc[r][0], x0, x1);
                    unpack2(acc[r][1], x2, x3);
                    float4 o = make_float4(x0 * m, x1 * m, x2 * m, x3 * m);
                    *reinterpret_cast<float4*>(&outV[((size_t)b * TOUT + t) * HID + c0]) = o;
                }
            }
        }
    } else {
        // fully masked tile: fv rows exactly zero
        for (int idx = j; idx < TTC * 64; idx += 256) {
            int r = idx >> 6, cc = idx & 63;
            int t = t0 + r;
            if (t < TOUT) {
                ulonglong2 z; z.x = 0ull; z.y = 0ull;
                *reinterpret_cast<ulonglong2*>(&outV[((size_t)b * TOUT + t) * HID + 4 * cc]) = z;
            }
        }
    }
}

// ---------------------------------------------------------------------------
extern "C" void kernel_launch(void* const* d_in, const int* in_sizes, int n_in,
                              void* d_out, int out_size)
{
    (void)in_sizes; (void)n_in; (void)out_size;
    const int*   code    = (const int*)  d_in[0];
    const float* others  = (const float*)d_in[1];
    const int*   length  = (const int*)  d_in[2];
    const int*   target  = (const int*)  d_in[3];
    const int*   widx    = (const int*)  d_in[4];
    const float* Wf      = (const float*)d_in[5];
    const float* bf      = (const float*)d_in[6];
    const float* Wb      = (const float*)d_in[7];
    const float* bb      = (const float*)d_in[8];
    const float* W0      = (const float*)d_in[9];
    const float* b0      = (const float*)d_in[10];
    const float* W1      = (const float*)d_in[11];
    const float* b1      = (const float*)d_in[12];

    float* outF = (float*)d_out;
    float* outB = outF + (size_t)BB * TOUT * HID;
    float* outV = outB + (size_t)BB * TOUT * HID;

    tgt_kernel<<<BB, 1024>>>(target, widx, Wf, Wb);
    kernelA<<<dim3(NTA, BB), 256>>>(code, others, length,
                                    Wf, bf, Wb, bb, W0, b0, outF, outB);
    kernelC<<<dim3(NTC, BB), 256>>>(length, W1, b1, outV);
}

// round 17
// speedup vs baseline: 1.1748x; 1.0144x over previous
#include <cuda_runtime.h>

typedef unsigned long long u64;

// ---------------- problem constants ----------------
#define BB    64
#define MAXV  200
#define PP    40
#define DOTH  57
#define KK    100
#define NCODE 507
#define TTA   8      // rows per block in kernel A (25 * 8 = 200 rows)
#define NTA   25
#define TTC   8      // t-steps per block in kernel C (25 * 8 = 200 >= 198)
#define NTC   25
#define TOUT  198
#define HID   256
#define WCW   768    // Wcat row width: 512 (Wf/Wb interleaved) + 256 (W0)

// Per-batch tgt contributions (time-invariant)
__device__ float g_tgtF[BB * HID];
__device__ float g_tgtB[BB * HID];
// h1 scratch (duplicated f32x2 format): ~26 MB
__device__ u64 g_h1d[(size_t)BB * MAXV * HID];
// concatenated gather weights: row c = [pair j: Wf(2f) Wb(2f)]x128 | W0 row(256f)
__device__ float g_Wcat[(size_t)NCODE * WCW];

// ---------------- packed f32x2 helpers ----------------
__device__ __forceinline__ u64 f2fma(u64 a, u64 b, u64 c) {
    u64 d; asm("fma.rn.f32x2 %0,%1,%2,%3;" : "=l"(d) : "l"(a), "l"(b), "l"(c)); return d;
}
__device__ __forceinline__ u64 f2add(u64 a, u64 b) {
    u64 d; asm("add.rn.f32x2 %0,%1,%2;" : "=l"(d) : "l"(a), "l"(b)); return d;
}
__device__ __forceinline__ u64 dup2(float v) {
    u64 d; asm("mov.b64 %0,{%1,%1};" : "=l"(d) : "f"(v)); return d;
}
__device__ __forceinline__ void unpack2(u64 v, float& x, float& y) {
    asm("mov.b64 {%0,%1},%2;" : "=f"(x), "=f"(y) : "l"(v));
}
__device__ __forceinline__ u64 ldg2(const float* __restrict__ p) {
    return *reinterpret_cast<const u64*>(p);
}
__device__ __forceinline__ ulonglong2 ldg4(const float* __restrict__ p) {
    return *reinterpret_cast<const ulonglong2*>(p);
}

// ---------------------------------------------------------------------------
// Kernel 1 (merged prep):
//   blocks [0,64):    per-batch tgt @ Wf[507:607] / Wb[507:607]
//   blocks [64,571):  build g_Wcat row (c = bid - 64)
// ---------------------------------------------------------------------------
__global__ __launch_bounds__(1024) void prep_kernel(
    const int* __restrict__ target, const int* __restrict__ widx,
    const float* __restrict__ Wf, const float* __restrict__ Wb,
    const float* __restrict__ W0)
{
    const int bid = blockIdx.x;
    const int j = threadIdx.x;
    if (bid >= BB) {
        // ---- Wcat build: row c ----
        const int c = bid - BB;
        if (j < 512) {
            int jc = j >> 2, sub = j & 3;
            float v = (sub < 2) ? Wf[(size_t)c * HID + 2 * jc + sub]
                                : Wb[(size_t)c * HID + 2 * jc + (sub - 2)];
            g_Wcat[(size_t)c * WCW + j] = v;
        } else if (j < 768) {
            g_Wcat[(size_t)c * WCW + j] = W0[(size_t)c * HID + (j - 512)];
        }
        return;
    }
    // ---- tgt part ----
    __shared__ int s_t[10];
    __shared__ u64 s_kf2[KK];
    __shared__ u64 s_part[1024];
    const int b = bid;
    if (j < 10) s_t[j] = target[b * 10 + j];
    __syncthreads();
    if (j < KK) {
        int w = widx[j];
        int keep = 1;
        #pragma unroll
        for (int q = 0; q < 10; q++) keep &= (s_t[q] != w);
        s_kf2[j] = dup2(keep ? 1.f : 0.f);
    }
    __syncthreads();
    const int pair = j & 127;
    const int m    = (j >> 7) & 1;
    const int kq   = j >> 8;
    const int c0   = 2 * pair;
    const float* W = m ? Wb : Wf;
    u64 a = 0ull;
    const int k0 = kq * 25;
    #pragma unroll
    for (int k = 0; k < 25; k++)
        a = f2fma(s_kf2[k0 + k], ldg2(W + (size_t)(507 + k0 + k) * HID + c0), a);
    s_part[j] = a;
    __syncthreads();
    if (kq == 0) {
        u64 t = f2add(f2add(a, s_part[j + 256]),
                      f2add(s_part[j + 512], s_part[j + 768]));
        float* dst = m ? g_tgtB : g_tgtF;
        *reinterpret_cast<u64*>(&dst[b * HID + c0]) = t;
    }
}

// ---------------------------------------------------------------------------
// Dedup within each row of PP codes (multi_hot duplicate collapse). -1 = skip.
// ---------------------------------------------------------------------------
__device__ __forceinline__ void dedup_codes(const int* __restrict__ s_codes,
                                            int* __restrict__ s_out, int j)
{
    for (int idx = j; idx < TTA * PP; idx += 256) {
        int p = idx % PP;
        int base = idx - p;
        int c = s_codes[idx];
        int take = 1;
        for (int q = 0; q < p; q++) take &= (s_codes[base + q] != c);
        s_out[idx] = take ? c : -1;
    }
}

// ---------------------------------------------------------------------------
// Dense feature accumulate: 4 rows, f32x2-packed (used by FV / W0 path).
// ---------------------------------------------------------------------------
__device__ __forceinline__ void dense_acc(
    u64* __restrict__ acc, const u64* __restrict__ sc, int stride, int nd,
    const float* __restrict__ W, int row0, int rbase, int c0)
{
    int i = 0;
    for (; i + 1 < nd; i += 2) {
        u64 w0 = ldg2(W + (size_t)(row0 + i) * HID + c0);
        u64 w1 = ldg2(W + (size_t)(row0 + i + 1) * HID + c0);
        #pragma unroll
        for (int lr = 0; lr < 4; lr++) {
            ulonglong2 s = *reinterpret_cast<const ulonglong2*>(&sc[(rbase + lr) * stride + i]);
            acc[lr] = f2fma(s.x, w0, acc[lr]);
            acc[lr] = f2fma(s.y, w1, acc[lr]);
        }
    }
    if (i < nd) {
        u64 w0 = ldg2(W + (size_t)(row0 + i) * HID + c0);
        #pragma unroll
        for (int lr = 0; lr < 4; lr++)
            acc[lr] = f2fma(sc[(rbase + lr) * stride + i], w0, acc[lr]);
    }
}

// ---------------------------------------------------------------------------
// Kernel A: unified per-row gathers via g_Wcat (one LDG.128 covers Wf+Wb,
// one LDG.64 covers W0). 128 col-pairs x 2 row-groups of 4 rows.
// ---------------------------------------------------------------------------
__global__ __launch_bounds__(256, 5) void kernelA(
    const int*   __restrict__ code,   const float* __restrict__ others,
    const int*   __restrict__ length,
    const float* __restrict__ Wf, const float* __restrict__ bf,
    const float* __restrict__ Wb, const float* __restrict__ bb,
    const float* __restrict__ W0, const float* __restrict__ b0,
    float* __restrict__ outF, float* __restrict__ outB)
{
    __shared__ int s_codes[TTA * PP];
    __shared__ int s_codes2[TTA * PP];
    __shared__ __align__(16) u64 s_scF[TTA * 58];   // cols 0..46 feat, 48..57 fwd interval
    __shared__ __align__(16) u64 s_scB[TTA * 12];   // 10 backward interval cols
    __shared__ __align__(16) u64 s_scV[TTA * 48];

    const int b  = blockIdx.y;
    const int v0 = blockIdx.x * TTA;
    const int j  = threadIdx.x;
    const int jc = j & 127;
    const int g  = j >> 7;
    const int c0 = 2 * jc;
    const int rbase = g * 4;
    const int L  = length[b];
    const bool fvA = (v0 <= L - 2);

    const float* oth = others + (size_t)b * MAXV * DOTH;
    const int*   cod = code   + (size_t)b * MAXV * PP;

    // ---- stage codes ----
    for (int idx = j; idx < TTA * PP; idx += 256) {
        int r = idx / PP, p = idx - r * PP;
        s_codes[idx] = cod[(v0 + r) * PP + p];
    }
    // ---- stage forward scalars: 47 feature cols at 0..46, interval at 48..57 ----
    for (int idx = j; idx < TTA * 57; idx += 256) {
        int r = idx / 57, i = idx - r * 57;
        int col, pos;
        if (i < 27)      { col = i;      pos = i; }
        else if (i < 47) { col = i + 10; pos = i; }
        else             { col = i - 20; pos = i + 1; }   // 48..57
        s_scF[r * 58 + pos] = dup2(oth[(v0 + r) * DOTH + col]);
    }
    // ---- stage backward interval scalars (10 cols) ----
    for (int idx = j; idx < TTA * 10; idx += 256) {
        int r = idx / 10, i = idx - r * 10;
        int v = v0 + r;
        float val;
        if (v == L - 1) val = 0.f;
        else {
            int w = (v <= L - 2) ? (v + 1) : ((v == L) ? 0 : (v - 1));
            val = oth[w * DOTH + 27 + i];
        }
        s_scB[r * 12 + i] = dup2(val);
    }
    // ---- stage FV scalars (48) for output t = v-1 ----
    if (fvA) {
        for (int idx = j; idx < TTA * 48; idx += 256) {
            int r = idx / 48, i = idx - r * 48;
            int v = v0 + r;
            float val;
            if (i < 20)      val = oth[v * DOTH + 37 + i];
            else if (i < 30) val = oth[v * DOTH + 7 + i];
            else if (i < 40) val = (v + 1 < MAXV) ? oth[(v + 1) * DOTH + (i - 3)] : 0.f;
            else             val = oth[v * DOTH + (i - 21)];
            s_scV[r * 48 + i] = dup2(val);
        }
    }
    __syncthreads();
    dedup_codes(s_codes, s_codes2, j);
    __syncthreads();

    u64 aF[4], aB[4], a0[4];
    {
        u64 baseF = f2add(ldg2(bf + c0), ldg2(&g_tgtF[b * HID + c0]));
        u64 baseB = f2add(ldg2(bb + c0), ldg2(&g_tgtB[b * HID + c0]));
        u64 base0 = fvA ? ldg2(b0 + c0) : 0ull;
        #pragma unroll
        for (int lr = 0; lr < 4; lr++) { aF[lr] = baseF; aB[lr] = baseB; a0[lr] = base0; }
    }

    // ---- merged gathers from Wcat: 1 LDG.128 (Wf,Wb) + 1 LDG.64 (W0) per code ----
    const float* Wc_fb = g_Wcat + 4 * jc;          // Wf/Wb interleaved pairs
    const float* Wc_0  = g_Wcat + 512 + c0;        // W0 region
    if (fvA) {
        #pragma unroll
        for (int lr = 0; lr < 4; lr++) {
            const int* cp = s_codes2 + (rbase + lr) * PP;
            u64 f = aF[lr], bk = aB[lr], z = a0[lr];
            #pragma unroll 4
            for (int p = 0; p < PP; p++) {
                int c = cp[p];
                size_t rowoff = (size_t)max(c, 0) * WCW;
                ulonglong2 fb = ldg4(Wc_fb + rowoff);
                u64 w0 = ldg2(Wc_0 + rowoff);
                if (c >= 0) { f = f2add(f, fb.x); bk = f2add(bk, fb.y); z = f2add(z, w0); }
            }
            aF[lr] = f; aB[lr] = bk; a0[lr] = z;
        }
    } else {
        #pragma unroll
        for (int lr = 0; lr < 4; lr++) {
            const int* cp = s_codes2 + (rbase + lr) * PP;
            u64 f = aF[lr], bk = aB[lr];
            #pragma unroll 4
            for (int p = 0; p < PP; p++) {
                int c = cp[p];
                size_t rowoff = (size_t)max(c, 0) * WCW;
                ulonglong2 fb = ldg4(Wc_fb + rowoff);
                if (c >= 0) { f = f2add(f, fb.x); bk = f2add(bk, fb.y); }
            }
            aF[lr] = f; aB[lr] = bk;
        }
    }

    // ---- MERGED dense features (47 shared cols, rows 607..653 of Wf AND Wb) ----
    {
        int i = 0;
        for (; i + 1 < 47; i += 2) {
            u64 wf0 = ldg2(Wf + (size_t)(607 + i) * HID + c0);
            u64 wf1 = ldg2(Wf + (size_t)(608 + i) * HID + c0);
            u64 wb0 = ldg2(Wb + (size_t)(607 + i) * HID + c0);
            u64 wb1 = ldg2(Wb + (size_t)(608 + i) * HID + c0);
            #pragma unroll
            for (int lr = 0; lr < 4; lr++) {
                ulonglong2 s = *reinterpret_cast<const ulonglong2*>(&s_scF[(rbase + lr) * 58 + i]);
                aF[lr] = f2fma(s.x, wf0, aF[lr]);
                aF[lr] = f2fma(s.y, wf1, aF[lr]);
                aB[lr] = f2fma(s.x, wb0, aB[lr]);
                aB[lr] = f2fma(s.y, wb1, aB[lr]);
            }
        }
        u64 wf = ldg2(Wf + (size_t)653 * HID + c0);
        u64 wb = ldg2(Wb + (size_t)653 * HID + c0);
        #pragma unroll
        for (int lr = 0; lr < 4; lr++) {
            u64 s = s_scF[(rbase + lr) * 58 + 46];
            aF[lr] = f2fma(s, wf, aF[lr]);
            aB[lr] = f2fma(s, wb, aB[lr]);
        }
    }
    // ---- forward interval (10 cols at s_scF 48..57, rows 654..663) ----
    #pragma unroll
    for (int i = 0; i < 10; i += 2) {
        u64 w0 = ldg2(Wf + (size_t)(654 + i) * HID + c0);
        u64 w1 = ldg2(Wf + (size_t)(655 + i) * HID + c0);
        #pragma unroll
        for (int lr = 0; lr < 4; lr++) {
            ulonglong2 s = *reinterpret_cast<const ulonglong2*>(&s_scF[(rbase + lr) * 58 + 48 + i]);
            aF[lr] = f2fma(s.x, w0, aF[lr]);
            aF[lr] = f2fma(s.y, w1, aF[lr]);
        }
    }
    // ---- backward interval (10 cols, rows 654..663) ----
    #pragma unroll
    for (int i = 0; i < 10; i += 2) {
        u64 w0 = ldg2(Wb + (size_t)(654 + i) * HID + c0);
        u64 w1 = ldg2(Wb + (size_t)(655 + i) * HID + c0);
        #pragma unroll
        for (int lr = 0; lr < 4; lr++) {
            ulonglong2 s = *reinterpret_cast<const ulonglong2*>(&s_scB[(rbase + lr) * 12 + i]);
            aB[lr] = f2fma(s.x, w0, aB[lr]);
            aB[lr] = f2fma(s.y, w1, aB[lr]);
        }
    }
    // ---- FV dense ----
    if (fvA) dense_acc(a0, s_scV, 48, 48, W0, 507, rbase, c0);

    // ---- stores ----
    #pragma unroll
    for (int lr = 0; lr < 4; lr++) {
        int v = v0 + rbase + lr;
        if (v < TOUT)
            *reinterpret_cast<u64*>(&outF[((size_t)b * TOUT + v) * HID + c0]) = aF[lr];
        int tb = (v < L) ? (L - 1 - v) : v;
        if (tb < TOUT)
            *reinterpret_cast<u64*>(&outB[((size_t)b * TOUT + tb) * HID + c0]) = aB[lr];
        if (fvA && v >= 1) {
            float x, y; unpack2(a0[lr], x, y);
            ulonglong2 hv;
            hv.x = dup2(fmaxf(x, 0.f));
            hv.y = dup2(fmaxf(y, 0.f));
            *reinterpret_cast<ulonglong2*>(&g_h1d[((size_t)b * MAXV + (v - 1)) * HID + c0]) = hv;
        }
    }
}

// ---------------------------------------------------------------------------
// Kernel C: W1 GEMM + L2 norm. Thread = (col-quad cq, K-segment ks of 64).
// All TTC=8 rows register-resident. Deterministic 4-segment combine.
// ---------------------------------------------------------------------------
__global__ __launch_bounds__(256, 4) void kernelC(
    const int* __restrict__ length,
    const float* __restrict__ W1, const float* __restrict__ b1,
    float* __restrict__ outV)
{
    __shared__ __align__(16) u64 s_h1d[TTC * HID];      // 16 KB
    __shared__ __align__(16) u64 s_part[3 * 64 * 16];   // 24 KB
    __shared__ float s_red[2 * TTC];
    __shared__ float s_rsq[TTC];

    const int b  = blockIdx.y;
    const int t0 = blockIdx.x * TTC;
    const int j  = threadIdx.x;
    const int cq = j & 63;
    const int ks = j >> 6;
    const int c0 = cq * 4;
    const int L  = length[b];

    if (t0 < L - 2) {
        {
            const ulonglong2* src = reinterpret_cast<const ulonglong2*>(
                &g_h1d[((size_t)b * MAXV + t0) * HID]);
            ulonglong2* dst = reinterpret_cast<ulonglong2*>(s_h1d);
            #pragma unroll
            for (int k = 0; k < 4; k++)
                dst[j + k * 256] = src[j + k * 256];
        }
        __syncthreads();

        u64 acc[TTC][2];
        {
            ulonglong2 init; init.x = 0ull; init.y = 0ull;
            if (ks == 0) init = ldg4(b1 + c0);
            #pragma unroll
            for (int r = 0; r < TTC; r++) { acc[r][0] = init.x; acc[r][1] = init.y; }
        }
        {
            const int i0 = ks * 64;
            const float* Wp = W1 + (size_t)i0 * HID + c0;
            const u64*   hp = s_h1d + i0;
            for (int i = 0; i < 64; i += 2) {
                ulonglong2 w0 = ldg4(Wp + (size_t)i * HID);
                ulonglong2 w1 = ldg4(Wp + (size_t)(i + 1) * HID);
                #pragma unroll
                for (int r = 0; r < TTC; r++) {
                    ulonglong2 h = *reinterpret_cast<const ulonglong2*>(&hp[r * HID + i]);
                    acc[r][0] = f2fma(h.x, w0.x, acc[r][0]);
                    acc[r][1] = f2fma(h.x, w0.y, acc[r][1]);
                    acc[r][0] = f2fma(h.y, w1.x, acc[r][0]);
                    acc[r][1] = f2fma(h.y, w1.y, acc[r][1]);
                }
            }
        }
        __syncthreads();
        if (ks > 0) {
            u64* dst = &s_part[((ks - 1) * 64 + cq) * 16];
            #pragma unroll
            for (int r = 0; r < TTC; r++) {
                dst[r * 2]     = acc[r][0];
                dst[r * 2 + 1] = acc[r][1];
            }
        }
        __syncthreads();
        if (ks == 0) {
            #pragma unroll
            for (int seg = 0; seg < 3; seg++) {
                const u64* src = &s_part[(seg * 64 + cq) * 16];
                #pragma unroll
                for (int r = 0; r < TTC; r++) {
                    acc[r][0] = f2add(acc[r][0], src[r * 2]);
                    acc[r][1] = f2add(acc[r][1], src[r * 2 + 1]);
                }
            }
            #pragma unroll
            for (int r = 0; r < TTC; r++) {
                float x0, x1, x2, x3;
                unpack2(acc[r][0], x0, x1);
                unpack2(acc[r][1], x2, x3);
                float v = x0 * x0 + x1 * x1 + x2 * x2 + x3 * x3;
                v += __shfl_xor_sync(0xffffffffu, v, 16);
                v += __shfl_xor_sync(0xffffffffu, v, 8);
                v += __shfl_xor_sync(0xffffffffu, v, 4);
                v += __shfl_xor_sync(0xffffffffu, v, 2);
                v += __shfl_xor_sync(0xffffffffu, v, 1);
                if ((j & 31) == 0) s_red[(j >> 5) * TTC + r] = v;
            }
        }
        __syncthreads();
        if (j < TTC) {
            float s = s_red[j] + s_red[TTC + j];
            float inv = rsqrtf(s);
            inv = inv * (1.5f - 0.5f * s * inv * inv);  // Newton step
            s_rsq[j] = inv;
        }
        __syncthreads();
        if (ks == 0) {
            #pragma unroll
            for (int r = 0; r < TTC; r++) {
                int t = t0 + r;
                if (t < TOUT) {
                    float m = (t < L - 2) ? s_rsq[r] : 0.f;
                    float x0, x1, x2, x3;
                    unpack2(acc[r][0], x0, x1);
                    unpack2(acc[r][1], x2, x3);
                    float4 o = make_float4(x0 * m, x1 * m, x2 * m, x3 * m);
                    *reinterpret_cast<float4*>(&outV[((size_t)b * TOUT + t) * HID + c0]) = o;
                }
            }
        }
    } else {
        for (int idx = j; idx < TTC * 64; idx += 256) {
            int r = idx >> 6, cc = idx & 63;
            int t = t0 + r;
            if (t < TOUT) {
                ulonglong2 z; z.x = 0ull; z.y = 0ull;
                *reinterpret_cast<ulonglong2*>(&outV[((size_t)b * TOUT + t) * HID + 4 * cc]) = z;
            }
        }
    }
}

// ---------------------------------------------------------------------------
extern "C" void kernel_launch(void* const* d_in, const int* in_sizes, int n_in,
                              void* d_out, int out_size)
{
    (void)in_sizes; (void)n_in; (void)out_size;
    const int*   code    = (const int*)  d_in[0];
    const float* others  = (const float*)d_in[1];
    const int*   length  = (const int*)  d_in[2];
    const int*   target  = (const int*)  d_in[3];
    const int*   widx    = (const int*)  d_in[4];
    const float* Wf      = (const float*)d_in[5];
    const float* bf      = (const float*)d_in[6];
    const float* Wb      = (const float*)d_in[7];
    const float* bb      = (const float*)d_in[8];
    const float* W0      = (const float*)d_in[9];
    const float* b0      = (const float*)d_in[10];
    const float* W1      = (const float*)d_in[11];
    const float* b1      = (const float*)d_in[12];

    float* outF = (float*)d_out;
    float* outB = outF + (size_t)BB * TOUT * HID;
    float* outV = outB + (size_t)BB * TOUT * HID;

    prep_kernel<<<BB + NCODE, 1024>>>(target, widx, Wf, Wb, W0);
    kernelA<<<dim3(NTA, BB), 256>>>(code, others, length,
                                    Wf, bf, Wb, bb, W0, b0, outF, outB);
    kernelC<<<dim3(NTC, BB), 256>>>(length, W1, b1, outV);
}